// round 14
// baseline (speedup 1.0000x reference)
#include <cuda_runtime.h>
#include <cuda_fp16.h>
#include <mma.h>
using namespace nvcuda;

#define NN 100000
#define NE 1600000
#define HID 64
#define ELLW 64                                   // slots per node (P(deg>64)~1e-20)

#define GDC_WAIT()   asm volatile("griddepcontrol.wait;" ::: "memory")
#define GDC_LAUNCH() asm volatile("griddepcontrol.launch_dependents;" ::: "memory")

// smem layout for the wmma GEMM (dynamic), 64-row tile
#define LDW 72                                    // halves per W row
#define LDX 72                                    // halves per X row
#define LDC 72                                    // floats per C row
#define TROWS 64                                  // tile rows per block
#define SW_BYTES (64 * LDW * 2)                   // 9216
#define SX_BYTES (TROWS * LDX * 2)                // 9216
#define SC_BYTES (TROWS * LDC * 4)                // 18432
#define SMEM_TOTAL (SW_BYTES + SX_BYTES + SC_BYTES)   // 36864 -> 6 blocks/SM

// ---- scratch (device globals: allocation-free) ----
__device__ int   g_is64;                          // 1 if edge_index is int64
__device__ __align__(16) int g_ell[NN * ELLW];    // ELL adjacency (src ids)
__device__ int   g_cur[NN];                       // per-node in-degree / cursor
__device__ float g_dinv[NN];                      // 1/sqrt(deg), deg = cur+1
__device__ __align__(16) __half g_Hh[NN * HID];   // (X@W)*dinv  (fp16 gather copy)
__device__ __align__(16) __half g_XA[NN * HID];   // ping-pong feature buffers (fp16)
__device__ __align__(16) __half g_XB[NN * HID];

__device__ __forceinline__ int clampi(int v, int hi) {
    return v < 0 ? 0 : (v >= hi ? hi - 1 : v);
}

__device__ __forceinline__ float4 h4_to_f4(uint2 v) {
    float2 f0 = __half22float2(*(const __half2*)&v.x);
    float2 f1 = __half22float2(*(const __half2*)&v.y);
    return make_float4(f0.x, f0.y, f1.x, f1.y);
}
__device__ __forceinline__ uint2 f4_to_h4(float4 f) {
    __half2 p0 = __float22half2_rn(make_float2(f.x, f.y));
    __half2 p1 = __float22half2_rn(make_float2(f.z, f.w));
    uint2 r;
    r.x = *(unsigned*)&p0;
    r.y = *(unsigned*)&p1;
    return r;
}

// ---------------------------------------------------------------------------
// Init: zero cursors; block 0 detects edge_index dtype (int64 buffers with
// ids < 2^31 have all-zero odd 32-bit words). First kernel: no wait needed.
// ---------------------------------------------------------------------------
__global__ void k_init(const unsigned* __restrict__ ei32) {
    GDC_LAUNCH();                         // successor prologue reads only inputs
    int i = blockIdx.x * 256 + threadIdx.x;
    if (i < NN) g_cur[i] = 0;
    if (blockIdx.x == 0) {
        int any = 0;
        for (int j = threadIdx.x; j < 2048; j += 256)
            if (ei32[2 * j + 1] != 0u) any = 1;
        any = __syncthreads_or(any);
        if (threadIdx.x == 0) g_is64 = any ? 0 : 1;
    }
}

// ELL append: 2 edges per thread. Pre-wait: int32-interpretation loads ONLY
// (always in-bounds for either dtype); int64 loads post-wait if needed.
__global__ void k_bucket(const void* __restrict__ eiv) {
    int t = blockIdx.x * blockDim.x + threadIdx.x;   // always < NE/2
    int2 ps32 = __ldg(&((const int2*)eiv)[t]);
    int2 pd32 = __ldg(&((const int2*)((const int*)eiv + NE))[t]);
    GDC_WAIT();
    GDC_LAUNCH();
    int s0, s1, d0, d1;
    if (g_is64) {
        longlong2 ps64 = __ldg(&((const longlong2*)eiv)[t]);
        longlong2 pd64 = __ldg(&((const longlong2*)((const long long*)eiv + NE))[t]);
        s0 = (int)ps64.x; s1 = (int)ps64.y;
        d0 = (int)pd64.x; d1 = (int)pd64.y;
    } else {
        s0 = ps32.x; s1 = ps32.y;
        d0 = pd32.x; d1 = pd32.y;
    }
    s0 = clampi(s0, NN); d0 = clampi(d0, NN);
    s1 = clampi(s1, NN); d1 = clampi(d1, NN);
    int p0 = atomicAdd(&g_cur[d0], 1);
    if (p0 < ELLW) g_ell[d0 * ELLW + p0] = s0;
    int p1 = atomicAdd(&g_cur[d1], 1);
    if (p1 < ELLW) g_ell[d1 * ELLW + p1] = s1;
}

// dinv from final degrees
__global__ void k_dinv() {               // grid 98, block 1024
    GDC_WAIT();
    GDC_LAUNCH();
    int i = blockIdx.x * 1024 + threadIdx.x;
    if (i < NN) g_dinv[i] = rsqrtf((float)(g_cur[i] + 1));
}

// ---------------------------------------------------------------------------
// Tensor-core GEMM + epilogue (wmma m16n16k16, fp16 in, fp32 accumulate):
//   H = X @ W ;  Hh = (H * dinv) fp16 for the gather;
//   Yinit = b + dinv^2 * H + (resid ? X : 0)   (stored fp16)
// Block: 256 thr = 8 warps, 64 rows. Warp w: m-tile (w&3), n-half (w>>2)
//   -> 16 rows x 32 cols, 4 k-steps x 2 n-tiles = 8 mmas.
// Prologue (pre-wait): W fp32 -> fp16 smem (pure input read) overlaps prev agg.
// ---------------------------------------------------------------------------
template <int FP16IN>
__global__ void __launch_bounds__(256) k_gemm(
                       const float* __restrict__ xext, int xsel,
                       const float* __restrict__ W,
                       const float* __restrict__ bias,
                       int ysel, int resid) {
    extern __shared__ char smem_raw[];
    __half* sW = (__half*)smem_raw;
    __half* sX = (__half*)(smem_raw + SW_BYTES);
    float*  sC = (float*)(smem_raw + SW_BYTES + SX_BYTES);

    const int tid = threadIdx.x;

    // ---- pre-wait prologue: W fp32 -> fp16 into sW (input-only reads) ----
    const float4* W4 = (const float4*)W;             // 1024 float4s (64x64)
    for (int i = tid; i < 1024; i += 256) {
        int r = i >> 4, c = (i & 15) * 4;
        float4 w = __ldg(&W4[i]);
        *(uint2*)&sW[r * LDW + c] = f4_to_h4(w);
    }

    GDC_WAIT();                                      // X, dinv now final
    GDC_LAUNCH();

    const int row0 = blockIdx.x * TROWS;
    const __half* xh = (xsel == 1) ? g_XA : g_XB;
    __half* Y = (ysel == 1) ? g_XA : g_XB;

    // ---- stage X tile (64 rows) into sX as fp16 ----
    if (FP16IN) {
        for (int i = tid; i < TROWS * 8; i += 256) { // uint4 = 8 halves
            int r = i >> 3, q = i & 7;
            int row = clampi(row0 + r, NN);
            uint4 v = __ldg(&((const uint4*)(xh + (size_t)row * HID))[q]);
            *(uint4*)&sX[r * LDX + q * 8] = v;
        }
    } else {
        for (int i = tid; i < TROWS * 16; i += 256) { // float4 = 4 halves
            int r = i >> 4, cg = i & 15;
            int row = clampi(row0 + r, NN);
            float4 v = __ldg(&((const float4*)(xext + (size_t)row * HID))[cg]);
            *(uint2*)&sX[r * LDX + cg * 4] = f4_to_h4(v);
        }
    }
    __syncthreads();

    // ---- wmma: warp w -> rows [16*(w&3), +16), cols [32*(w>>2), +32) ----
    {
        int w  = tid >> 5;
        int mt = w & 3;
        int nh = w >> 2;
        wmma::fragment<wmma::accumulator, 16, 16, 16, float> c[2];
#pragma unroll
        for (int n = 0; n < 2; n++) wmma::fill_fragment(c[n], 0.0f);
#pragma unroll
        for (int k = 0; k < 4; k++) {
            wmma::fragment<wmma::matrix_a, 16, 16, 16, __half, wmma::row_major> a;
            wmma::load_matrix_sync(a, sX + (16 * mt) * LDX + 16 * k, LDX);
#pragma unroll
            for (int n = 0; n < 2; n++) {
                wmma::fragment<wmma::matrix_b, 16, 16, 16, __half, wmma::row_major> b;
                wmma::load_matrix_sync(b, sW + (16 * k) * LDW + 16 * (2 * nh + n), LDW);
                wmma::mma_sync(c[n], a, b, c[n]);
            }
        }
#pragma unroll
        for (int n = 0; n < 2; n++)
            wmma::store_matrix_sync(sC + (16 * mt) * LDC + 16 * (2 * nh + n),
                                    c[n], LDC, wmma::mem_row_major);
    }
    __syncthreads();

    // ---- epilogue: Hh + Yinit (fp32 math, fp16 stores) ----
    for (int i = tid; i < TROWS * 16; i += 256) {
        int r = i >> 4, cg = i & 15;
        int row = row0 + r;
        if (row >= NN) continue;
        float4 h = *(float4*)&sC[r * LDC + cg * 4];
        float dv = g_dinv[row];
        // fp16 pre-scaled copy for the gather: Hh = H * dinv
        ((uint2*)g_Hh)[(size_t)row * 16 + cg] =
            f4_to_h4(make_float4(h.x * dv, h.y * dv, h.z * dv, h.w * dv));
        // Y init: bias + self-loop + residual
        float d2 = dv * dv;
        float4 b4 = __ldg(&((const float4*)bias)[cg]);
        float4 y = make_float4(b4.x + h.x * d2, b4.y + h.y * d2,
                               b4.z + h.z * d2, b4.w + h.w * d2);
        if (FP16IN && resid) {
            float4 xv = h4_to_f4(*(uint2*)&sX[r * LDX + cg * 4]); // post-ReLU
            y.x += xv.x; y.y += xv.y; y.z += xv.z; y.w += xv.w;
        }
        ((uint2*)Y)[(size_t)row * 16 + cg] = f4_to_h4(y);
    }
}

// ---------------------------------------------------------------------------
// Aggregate: one warp per node, atomic-free ELL gather (fp16 reads, fp32 acc).
//   a = Yinit[node] + dinv[node] * sum_e Hh[src_e] ;  X = relu(a)
// Final layer (classify=1): out[node] = X @ Wc + bc instead of storing X.
// ---------------------------------------------------------------------------
__global__ void __launch_bounds__(256) k_agg(int ysel,
                      const float* __restrict__ Wc,
                      const float* __restrict__ bc,
                      float* __restrict__ out, int classify) {
    int gid  = blockIdx.x * blockDim.x + threadIdx.x;
    int node = gid >> 5;
    int lane = gid & 31;

    // pre-wait: ELL metadata is final (transitively guaranteed complete)
    int k    = min(g_cur[node], ELLW);
    float dv = g_dinv[node];

    GDC_WAIT();                                  // Hh, Yinit now final
    GDC_LAUNCH();

    __half* Y = (ysel == 1) ? g_XA : g_XB;
    const int* adj = g_ell + node * ELLW;
    const __half2* H2 = (const __half2*)g_Hh;

    float2 s = make_float2(0.f, 0.f);
#pragma unroll 8
    for (int j = 0; j < k; j++) {
        int e = __ldg(&adj[j]);                  // broadcast (uniform addr)
        float2 h = __half22float2(__ldg(&H2[(size_t)e * 32 + lane]));
        s.x += h.x;
        s.y += h.y;
    }

    float2 a = __half22float2(((__half2*)Y)[(size_t)node * 32 + lane]);
    a.x = fmaxf(a.x + dv * s.x, 0.f);
    a.y = fmaxf(a.y + dv * s.y, 0.f);

    if (!classify) {
        ((__half2*)Y)[(size_t)node * 32 + lane] = __float22half2_rn(a);
    } else {
        int f = 2 * lane;                        // features f, f+1
        float c0 = a.x * __ldg(&Wc[f * 3 + 0]) + a.y * __ldg(&Wc[f * 3 + 3]);
        float c1 = a.x * __ldg(&Wc[f * 3 + 1]) + a.y * __ldg(&Wc[f * 3 + 4]);
        float c2 = a.x * __ldg(&Wc[f * 3 + 2]) + a.y * __ldg(&Wc[f * 3 + 5]);
#pragma unroll
        for (int o = 16; o > 0; o >>= 1) {
            c0 += __shfl_down_sync(0xffffffffu, c0, o);
            c1 += __shfl_down_sync(0xffffffffu, c1, o);
            c2 += __shfl_down_sync(0xffffffffu, c2, o);
        }
        if (lane == 0) {
            out[node * 3 + 0] = c0 + __ldg(&bc[0]);
            out[node * 3 + 1] = c1 + __ldg(&bc[1]);
            out[node * 3 + 2] = c2 + __ldg(&bc[2]);
        }
    }
}

// ---------------------------------------------------------------------------
template <typename F, typename... Args>
static inline void pdl(F kern, int grid, int block, size_t smem, Args... args) {
    cudaLaunchConfig_t cfg = {};
    cfg.gridDim  = dim3(grid, 1, 1);
    cfg.blockDim = dim3(block, 1, 1);
    cfg.dynamicSmemBytes = smem;
    cfg.stream   = 0;                 // same default-stream semantics as <<<>>>
    cudaLaunchAttribute attr[1];
    attr[0].id = cudaLaunchAttributeProgrammaticStreamSerialization;
    attr[0].val.programmaticStreamSerializationAllowed = 1;
    cfg.attrs = attr;
    cfg.numAttrs = 1;
    cudaLaunchKernelEx(&cfg, kern, args...);
}

extern "C" void kernel_launch(void* const* d_in, const int* in_sizes, int n_in,
                              void* d_out, int out_size) {
    const float* x  = (const float*)d_in[0];
    const void*  ei = d_in[1];
    const float* Ws = (const float*)d_in[2];
    const float* bs = (const float*)d_in[3];
    const float* Wc = (const float*)d_in[4];
    const float* bc = (const float*)d_in[5];
    float* out = (float*)d_out;

    cudaFuncSetAttribute(k_gemm<0>, cudaFuncAttributeMaxDynamicSharedMemorySize,
                         SMEM_TOTAL);
    cudaFuncSetAttribute(k_gemm<1>, cudaFuncAttributeMaxDynamicSharedMemorySize,
                         SMEM_TOTAL);

    // ---- ELL adjacency build (PDL-chained; no count/scan passes) ----
    pdl(k_init,   (NN + 255) / 256, 256, 0, (const unsigned*)ei);
    pdl(k_bucket, NE / 512, 256, 0, ei);
    pdl(k_dinv,   98, 1024, 0);

    // ---- 4 GCN layers (layer 3 fuses the classifier) ----
    const int gemm_grid = (NN + TROWS - 1) / TROWS;
    const int agg_grid  = NN * 32 / 256;
    int sel = 0;                                    // 0=x, 1=g_XA, 2=g_XB
    for (int l = 0; l < 4; l++) {
        int osel = (l & 1) ? 2 : 1;
        const float* W = Ws + l * HID * HID;
        const float* b = bs + l * HID;
        if (l == 0)
            pdl(k_gemm<0>, gemm_grid, 256, SMEM_TOTAL, x, sel, W, b, osel, 0);
        else
            pdl(k_gemm<1>, gemm_grid, 256, SMEM_TOTAL, x, sel, W, b, osel, 1);
        pdl(k_agg, agg_grid, 256, 0, osel, Wc, bc, out, (l == 3) ? 1 : 0);
        sel = osel;
    }
}

// round 15
// speedup vs baseline: 1.0040x; 1.0040x over previous
#include <cuda_runtime.h>
#include <cuda_fp16.h>
#include <mma.h>
using namespace nvcuda;

#define NN 100000
#define NE 1600000
#define HID 64
#define ELLW 64                                   // slots per node (P(deg>64)~1e-20)

#define GDC_WAIT()   asm volatile("griddepcontrol.wait;" ::: "memory")
#define GDC_LAUNCH() asm volatile("griddepcontrol.launch_dependents;" ::: "memory")

// smem layout for the wmma GEMM (dynamic), 64-row tile
#define LDW 72                                    // halves per W row
#define LDX 72                                    // halves per X row
#define LDC 72                                    // floats per C row
#define TROWS 64                                  // tile rows per block
#define SW_BYTES (64 * LDW * 2)                   // 9216
#define SX_BYTES (TROWS * LDX * 2)                // 9216
#define SC_BYTES (TROWS * LDC * 4)                // 18432
#define SMEM_TOTAL (SW_BYTES + SX_BYTES + SC_BYTES)   // 36864 -> 6 blocks/SM

// ---- scratch (device globals: allocation-free) ----
__device__ int   g_is64;                          // 1 if edge_index is int64
__device__ __align__(16) int g_ell[NN * ELLW];    // ELL adjacency (src ids)
__device__ int   g_cur[NN];                       // per-node in-degree / cursor
__device__ float g_dinv[NN];                      // 1/sqrt(deg), deg = cur+1
__device__ __align__(16) __half g_Hh[NN * HID];   // (X@W)*dinv  (fp16 gather copy)
__device__ __align__(16) __half g_XA[NN * HID];   // ping-pong feature buffers (fp16)
__device__ __align__(16) __half g_XB[NN * HID];

__device__ __forceinline__ int clampi(int v, int hi) {
    return v < 0 ? 0 : (v >= hi ? hi - 1 : v);
}

__device__ __forceinline__ float4 h4_to_f4(uint2 v) {
    float2 f0 = __half22float2(*(const __half2*)&v.x);
    float2 f1 = __half22float2(*(const __half2*)&v.y);
    return make_float4(f0.x, f0.y, f1.x, f1.y);
}
__device__ __forceinline__ uint2 f4_to_h4(float4 f) {
    __half2 p0 = __float22half2_rn(make_float2(f.x, f.y));
    __half2 p1 = __float22half2_rn(make_float2(f.z, f.w));
    uint2 r;
    r.x = *(unsigned*)&p0;
    r.y = *(unsigned*)&p1;
    return r;
}

// ---------------------------------------------------------------------------
// Init: zero cursors; block 0 detects edge_index dtype (int64 buffers with
// ids < 2^31 have all-zero odd 32-bit words). First kernel: no wait needed.
// ---------------------------------------------------------------------------
__global__ void k_init(const unsigned* __restrict__ ei32) {
    GDC_LAUNCH();                         // successor prologue reads only inputs
    int i = blockIdx.x * 256 + threadIdx.x;
    if (i < NN) g_cur[i] = 0;
    if (blockIdx.x == 0) {
        int any = 0;
        for (int j = threadIdx.x; j < 2048; j += 256)
            if (ei32[2 * j + 1] != 0u) any = 1;
        any = __syncthreads_or(any);
        if (threadIdx.x == 0) g_is64 = any ? 0 : 1;
    }
}

// ELL append: 2 edges per thread. Pre-wait: int32-interpretation loads ONLY
// (always in-bounds for either dtype); int64 loads post-wait if needed.
__global__ void k_bucket(const void* __restrict__ eiv) {
    int t = blockIdx.x * blockDim.x + threadIdx.x;   // always < NE/2
    int2 ps32 = __ldg(&((const int2*)eiv)[t]);
    int2 pd32 = __ldg(&((const int2*)((const int*)eiv + NE))[t]);
    GDC_WAIT();
    GDC_LAUNCH();
    int s0, s1, d0, d1;
    if (g_is64) {
        longlong2 ps64 = __ldg(&((const longlong2*)eiv)[t]);
        longlong2 pd64 = __ldg(&((const longlong2*)((const long long*)eiv + NE))[t]);
        s0 = (int)ps64.x; s1 = (int)ps64.y;
        d0 = (int)pd64.x; d1 = (int)pd64.y;
    } else {
        s0 = ps32.x; s1 = ps32.y;
        d0 = pd32.x; d1 = pd32.y;
    }
    s0 = clampi(s0, NN); d0 = clampi(d0, NN);
    s1 = clampi(s1, NN); d1 = clampi(d1, NN);
    int p0 = atomicAdd(&g_cur[d0], 1);
    if (p0 < ELLW) g_ell[d0 * ELLW + p0] = s0;
    int p1 = atomicAdd(&g_cur[d1], 1);
    if (p1 < ELLW) g_ell[d1 * ELLW + p1] = s1;
}

// dinv from final degrees
__global__ void k_dinv() {               // grid 98, block 1024
    GDC_WAIT();
    GDC_LAUNCH();
    int i = blockIdx.x * 1024 + threadIdx.x;
    if (i < NN) g_dinv[i] = rsqrtf((float)(g_cur[i] + 1));
}

// ---------------------------------------------------------------------------
// Tensor-core GEMM + epilogue (wmma m16n16k16, fp16 in, fp32 accumulate):
//   H = X @ W ;  Hh = (H * dinv) fp16 for the gather;
//   Yinit = b + dinv^2 * H + (resid ? X : 0)   (stored fp16)
// Block: 256 thr = 8 warps, 64 rows. Warp w: m-tile (w&3), n-half (w>>2)
//   -> 16 rows x 32 cols, 4 k-steps x 2 n-tiles = 8 mmas.
// Prologue (pre-wait): W fp32 -> fp16 smem (pure input read) overlaps prev agg.
// ---------------------------------------------------------------------------
template <int FP16IN>
__global__ void __launch_bounds__(256) k_gemm(
                       const float* __restrict__ xext, int xsel,
                       const float* __restrict__ W,
                       const float* __restrict__ bias,
                       int ysel, int resid) {
    extern __shared__ char smem_raw[];
    __half* sW = (__half*)smem_raw;
    __half* sX = (__half*)(smem_raw + SW_BYTES);
    float*  sC = (float*)(smem_raw + SW_BYTES + SX_BYTES);

    const int tid = threadIdx.x;

    // ---- pre-wait prologue: W fp32 -> fp16 into sW (input-only reads) ----
    const float4* W4 = (const float4*)W;             // 1024 float4s (64x64)
    for (int i = tid; i < 1024; i += 256) {
        int r = i >> 4, c = (i & 15) * 4;
        float4 w = __ldg(&W4[i]);
        *(uint2*)&sW[r * LDW + c] = f4_to_h4(w);
    }

    GDC_WAIT();                                      // X, dinv now final
    GDC_LAUNCH();

    const int row0 = blockIdx.x * TROWS;
    const __half* xh = (xsel == 1) ? g_XA : g_XB;
    __half* Y = (ysel == 1) ? g_XA : g_XB;

    // ---- stage X tile (64 rows) into sX as fp16 ----
    if (FP16IN) {
        for (int i = tid; i < TROWS * 8; i += 256) { // uint4 = 8 halves
            int r = i >> 3, q = i & 7;
            int row = clampi(row0 + r, NN);
            uint4 v = __ldg(&((const uint4*)(xh + (size_t)row * HID))[q]);
            *(uint4*)&sX[r * LDX + q * 8] = v;
        }
    } else {
        for (int i = tid; i < TROWS * 16; i += 256) { // float4 = 4 halves
            int r = i >> 4, cg = i & 15;
            int row = clampi(row0 + r, NN);
            float4 v = __ldg(&((const float4*)(xext + (size_t)row * HID))[cg]);
            *(uint2*)&sX[r * LDX + cg * 4] = f4_to_h4(v);
        }
    }
    __syncthreads();

    // ---- wmma: warp w -> rows [16*(w&3), +16), cols [32*(w>>2), +32) ----
    {
        int w  = tid >> 5;
        int mt = w & 3;
        int nh = w >> 2;
        wmma::fragment<wmma::accumulator, 16, 16, 16, float> c[2];
#pragma unroll
        for (int n = 0; n < 2; n++) wmma::fill_fragment(c[n], 0.0f);
#pragma unroll
        for (int k = 0; k < 4; k++) {
            wmma::fragment<wmma::matrix_a, 16, 16, 16, __half, wmma::row_major> a;
            wmma::load_matrix_sync(a, sX + (16 * mt) * LDX + 16 * k, LDX);
#pragma unroll
            for (int n = 0; n < 2; n++) {
                wmma::fragment<wmma::matrix_b, 16, 16, 16, __half, wmma::row_major> b;
                wmma::load_matrix_sync(b, sW + (16 * k) * LDW + 16 * (2 * nh + n), LDW);
                wmma::mma_sync(c[n], a, b, c[n]);
            }
        }
#pragma unroll
        for (int n = 0; n < 2; n++)
            wmma::store_matrix_sync(sC + (16 * mt) * LDC + 16 * (2 * nh + n),
                                    c[n], LDC, wmma::mem_row_major);
    }
    __syncthreads();

    // ---- epilogue: Hh + Yinit (fp32 math, fp16 stores) ----
    for (int i = tid; i < TROWS * 16; i += 256) {
        int r = i >> 4, cg = i & 15;
        int row = row0 + r;
        if (row >= NN) continue;
        float4 h = *(float4*)&sC[r * LDC + cg * 4];
        float dv = g_dinv[row];
        // fp16 pre-scaled copy for the gather: Hh = H * dinv
        ((uint2*)g_Hh)[(size_t)row * 16 + cg] =
            f4_to_h4(make_float4(h.x * dv, h.y * dv, h.z * dv, h.w * dv));
        // Y init: bias + self-loop + residual
        float d2 = dv * dv;
        float4 b4 = __ldg(&((const float4*)bias)[cg]);
        float4 y = make_float4(b4.x + h.x * d2, b4.y + h.y * d2,
                               b4.z + h.z * d2, b4.w + h.w * d2);
        if (FP16IN && resid) {
            float4 xv = h4_to_f4(*(uint2*)&sX[r * LDX + cg * 4]); // post-ReLU
            y.x += xv.x; y.y += xv.y; y.z += xv.z; y.w += xv.w;
        }
        ((uint2*)Y)[(size_t)row * 16 + cg] = f4_to_h4(y);
    }
}

// ---------------------------------------------------------------------------
// Aggregate: one warp per node, atomic-free ELL gather (fp16 reads, fp32 acc).
//   a = Yinit[node] + dinv[node] * sum_e Hh[src_e] ;  X = relu(a)
// Final layer (classify=1): out[node] = X @ Wc + bc instead of storing X.
// ---------------------------------------------------------------------------
__global__ void __launch_bounds__(256) k_agg(int ysel,
                      const float* __restrict__ Wc,
                      const float* __restrict__ bc,
                      float* __restrict__ out, int classify) {
    int gid  = blockIdx.x * blockDim.x + threadIdx.x;
    int node = gid >> 5;
    int lane = gid & 31;

    // pre-wait: ELL metadata is final (transitively guaranteed complete)
    int k    = min(g_cur[node], ELLW);
    float dv = g_dinv[node];

    GDC_WAIT();                                  // Hh, Yinit now final
    GDC_LAUNCH();

    __half* Y = (ysel == 1) ? g_XA : g_XB;
    const int* adj = g_ell + node * ELLW;
    const __half2* H2 = (const __half2*)g_Hh;

    float2 s = make_float2(0.f, 0.f);
#pragma unroll 8
    for (int j = 0; j < k; j++) {
        int e = __ldg(&adj[j]);                  // broadcast (uniform addr)
        float2 h = __half22float2(__ldg(&H2[(size_t)e * 32 + lane]));
        s.x += h.x;
        s.y += h.y;
    }

    float2 a = __half22float2(((__half2*)Y)[(size_t)node * 32 + lane]);
    a.x = fmaxf(a.x + dv * s.x, 0.f);
    a.y = fmaxf(a.y + dv * s.y, 0.f);

    if (!classify) {
        ((__half2*)Y)[(size_t)node * 32 + lane] = __float22half2_rn(a);
    } else {
        int f = 2 * lane;                        // features f, f+1
        float c0 = a.x * __ldg(&Wc[f * 3 + 0]) + a.y * __ldg(&Wc[f * 3 + 3]);
        float c1 = a.x * __ldg(&Wc[f * 3 + 1]) + a.y * __ldg(&Wc[f * 3 + 4]);
        float c2 = a.x * __ldg(&Wc[f * 3 + 2]) + a.y * __ldg(&Wc[f * 3 + 5]);
#pragma unroll
        for (int o = 16; o > 0; o >>= 1) {
            c0 += __shfl_down_sync(0xffffffffu, c0, o);
            c1 += __shfl_down_sync(0xffffffffu, c1, o);
            c2 += __shfl_down_sync(0xffffffffu, c2, o);
        }
        if (lane == 0) {
            out[node * 3 + 0] = c0 + __ldg(&bc[0]);
            out[node * 3 + 1] = c1 + __ldg(&bc[1]);
            out[node * 3 + 2] = c2 + __ldg(&bc[2]);
        }
    }
}

// ---------------------------------------------------------------------------
template <typename F, typename... Args>
static inline void pdl(F kern, int grid, int block, size_t smem, Args... args) {
    cudaLaunchConfig_t cfg = {};
    cfg.gridDim  = dim3(grid, 1, 1);
    cfg.blockDim = dim3(block, 1, 1);
    cfg.dynamicSmemBytes = smem;
    cfg.stream   = 0;                 // same default-stream semantics as <<<>>>
    cudaLaunchAttribute attr[1];
    attr[0].id = cudaLaunchAttributeProgrammaticStreamSerialization;
    attr[0].val.programmaticStreamSerializationAllowed = 1;
    cfg.attrs = attr;
    cfg.numAttrs = 1;
    cudaLaunchKernelEx(&cfg, kern, args...);
}

extern "C" void kernel_launch(void* const* d_in, const int* in_sizes, int n_in,
                              void* d_out, int out_size) {
    const float* x  = (const float*)d_in[0];
    const void*  ei = d_in[1];
    const float* Ws = (const float*)d_in[2];
    const float* bs = (const float*)d_in[3];
    const float* Wc = (const float*)d_in[4];
    const float* bc = (const float*)d_in[5];
    float* out = (float*)d_out;

    cudaFuncSetAttribute(k_gemm<0>, cudaFuncAttributeMaxDynamicSharedMemorySize,
                         SMEM_TOTAL);
    cudaFuncSetAttribute(k_gemm<1>, cudaFuncAttributeMaxDynamicSharedMemorySize,
                         SMEM_TOTAL);

    // ---- ELL adjacency build (PDL-chained; no count/scan passes) ----
    pdl(k_init,   (NN + 255) / 256, 256, 0, (const unsigned*)ei);
    pdl(k_bucket, NE / 512, 256, 0, ei);
    pdl(k_dinv,   98, 1024, 0);

    // ---- 4 GCN layers (layer 3 fuses the classifier) ----
    const int gemm_grid = (NN + TROWS - 1) / TROWS;
    const int agg_grid  = NN * 32 / 256;
    int sel = 0;                                    // 0=x, 1=g_XA, 2=g_XB
    for (int l = 0; l < 4; l++) {
        int osel = (l & 1) ? 2 : 1;
        const float* W = Ws + l * HID * HID;
        const float* b = bs + l * HID;
        if (l == 0)
            pdl(k_gemm<0>, gemm_grid, 256, SMEM_TOTAL, x, sel, W, b, osel, 0);
        else
            pdl(k_gemm<1>, gemm_grid, 256, SMEM_TOTAL, x, sel, W, b, osel, 1);
        pdl(k_agg, agg_grid, 256, 0, osel, Wc, bc, out, (l == 3) ? 1 : 0);
        sel = osel;
    }
}

// round 16
// speedup vs baseline: 1.0074x; 1.0034x over previous
#include <cuda_runtime.h>
#include <cuda_fp16.h>
#include <mma.h>
using namespace nvcuda;

#define NN 100000
#define NE 1600000
#define HID 64
#define ELLW 64                                   // slots per node (P(deg>64)~1e-20)

#define GDC_WAIT()   asm volatile("griddepcontrol.wait;" ::: "memory")
#define GDC_LAUNCH() asm volatile("griddepcontrol.launch_dependents;" ::: "memory")

// smem layout for the wmma GEMM (dynamic), 64-row tile
#define LDW 72                                    // halves per W row
#define LDX 72                                    // halves per X row
#define LDC 72                                    // floats per C row
#define TROWS 64                                  // tile rows per block
#define SW_BYTES (64 * LDW * 2)                   // 9216
#define SX_BYTES (TROWS * LDX * 2)                // 9216
#define SC_BYTES (TROWS * LDC * 4)                // 18432
#define SMEM_TOTAL (SW_BYTES + SX_BYTES + SC_BYTES)   // 36864 -> 6 blocks/SM

// ---- scratch (device globals: allocation-free) ----
__device__ int   g_is64;                          // 1 if edge_index is int64
__device__ __align__(16) int g_ell[NN * ELLW];    // ELL adjacency (src ids)
__device__ int   g_cur[NN];                       // per-node in-degree / cursor
__device__ float g_dinv[NN];                      // 1/sqrt(deg), deg = cur+1
__device__ __align__(16) __half g_Hh[NN * HID];   // (X@W)*dinv  (fp16 gather copy)
__device__ __align__(16) __half g_XA[NN * HID];   // ping-pong feature buffers (fp16)
__device__ __align__(16) __half g_XB[NN * HID];

__device__ __forceinline__ int clampi(int v, int hi) {
    return v < 0 ? 0 : (v >= hi ? hi - 1 : v);
}

__device__ __forceinline__ float4 h4_to_f4(uint2 v) {
    float2 f0 = __half22float2(*(const __half2*)&v.x);
    float2 f1 = __half22float2(*(const __half2*)&v.y);
    return make_float4(f0.x, f0.y, f1.x, f1.y);
}
__device__ __forceinline__ uint2 f4_to_h4(float4 f) {
    __half2 p0 = __float22half2_rn(make_float2(f.x, f.y));
    __half2 p1 = __float22half2_rn(make_float2(f.z, f.w));
    uint2 r;
    r.x = *(unsigned*)&p0;
    r.y = *(unsigned*)&p1;
    return r;
}

// ---------------------------------------------------------------------------
// Init: zero cursors; block 0 detects edge_index dtype (int64 buffers with
// ids < 2^31 have all-zero odd 32-bit words). First kernel: no wait needed.
// ---------------------------------------------------------------------------
__global__ void k_init(const unsigned* __restrict__ ei32) {
    GDC_LAUNCH();                         // successor prologue reads only inputs
    int i = blockIdx.x * 256 + threadIdx.x;
    if (i < NN) g_cur[i] = 0;
    if (blockIdx.x == 0) {
        int any = 0;
        for (int j = threadIdx.x; j < 2048; j += 256)
            if (ei32[2 * j + 1] != 0u) any = 1;
        any = __syncthreads_or(any);
        if (threadIdx.x == 0) g_is64 = any ? 0 : 1;
    }
}

// ELL append: 2 edges per thread. Pre-wait: int32-interpretation loads ONLY
// (always in-bounds for either dtype); int64 loads post-wait if needed.
__global__ void k_bucket(const void* __restrict__ eiv) {
    int t = blockIdx.x * blockDim.x + threadIdx.x;   // always < NE/2
    int2 ps32 = __ldg(&((const int2*)eiv)[t]);
    int2 pd32 = __ldg(&((const int2*)((const int*)eiv + NE))[t]);
    GDC_WAIT();
    GDC_LAUNCH();
    int s0, s1, d0, d1;
    if (g_is64) {
        longlong2 ps64 = __ldg(&((const longlong2*)eiv)[t]);
        longlong2 pd64 = __ldg(&((const longlong2*)((const long long*)eiv + NE))[t]);
        s0 = (int)ps64.x; s1 = (int)ps64.y;
        d0 = (int)pd64.x; d1 = (int)pd64.y;
    } else {
        s0 = ps32.x; s1 = ps32.y;
        d0 = pd32.x; d1 = pd32.y;
    }
    s0 = clampi(s0, NN); d0 = clampi(d0, NN);
    s1 = clampi(s1, NN); d1 = clampi(d1, NN);
    int p0 = atomicAdd(&g_cur[d0], 1);
    if (p0 < ELLW) g_ell[d0 * ELLW + p0] = s0;
    int p1 = atomicAdd(&g_cur[d1], 1);
    if (p1 < ELLW) g_ell[d1 * ELLW + p1] = s1;
}

// dinv from final degrees
__global__ void k_dinv() {               // grid 98, block 1024
    GDC_WAIT();
    GDC_LAUNCH();
    int i = blockIdx.x * 1024 + threadIdx.x;
    if (i < NN) g_dinv[i] = rsqrtf((float)(g_cur[i] + 1));
}

// ---------------------------------------------------------------------------
// Tensor-core GEMM + epilogue (wmma m16n16k16, fp16 in, fp32 accumulate):
//   H = X @ W ;  Hh = (H * dinv) fp16 for the gather;
//   Yinit = b + dinv^2 * H + (resid ? X : 0)   (stored fp16)
// Block: 256 thr = 8 warps, 64 rows. Warp w: m-tile (w&3), n-half (w>>2)
//   -> 16 rows x 32 cols, 4 k-steps x 2 n-tiles = 8 mmas.
// Prologue (pre-wait): W fp32 -> fp16 smem (pure input read) overlaps prev agg.
// ---------------------------------------------------------------------------
template <int FP16IN>
__global__ void __launch_bounds__(256) k_gemm(
                       const float* __restrict__ xext, int xsel,
                       const float* __restrict__ W,
                       const float* __restrict__ bias,
                       int ysel, int resid) {
    extern __shared__ char smem_raw[];
    __half* sW = (__half*)smem_raw;
    __half* sX = (__half*)(smem_raw + SW_BYTES);
    float*  sC = (float*)(smem_raw + SW_BYTES + SX_BYTES);

    const int tid = threadIdx.x;

    // ---- pre-wait prologue: W fp32 -> fp16 into sW (input-only reads) ----
    const float4* W4 = (const float4*)W;             // 1024 float4s (64x64)
    for (int i = tid; i < 1024; i += 256) {
        int r = i >> 4, c = (i & 15) * 4;
        float4 w = __ldg(&W4[i]);
        *(uint2*)&sW[r * LDW + c] = f4_to_h4(w);
    }

    GDC_WAIT();                                      // X, dinv now final
    GDC_LAUNCH();

    const int row0 = blockIdx.x * TROWS;
    const __half* xh = (xsel == 1) ? g_XA : g_XB;
    __half* Y = (ysel == 1) ? g_XA : g_XB;

    // ---- stage X tile (64 rows) into sX as fp16 ----
    if (FP16IN) {
        for (int i = tid; i < TROWS * 8; i += 256) { // uint4 = 8 halves
            int r = i >> 3, q = i & 7;
            int row = clampi(row0 + r, NN);
            uint4 v = __ldg(&((const uint4*)(xh + (size_t)row * HID))[q]);
            *(uint4*)&sX[r * LDX + q * 8] = v;
        }
    } else {
        for (int i = tid; i < TROWS * 16; i += 256) { // float4 = 4 halves
            int r = i >> 4, cg = i & 15;
            int row = clampi(row0 + r, NN);
            float4 v = __ldg(&((const float4*)(xext + (size_t)row * HID))[cg]);
            *(uint2*)&sX[r * LDX + cg * 4] = f4_to_h4(v);
        }
    }
    __syncthreads();

    // ---- wmma: warp w -> rows [16*(w&3), +16), cols [32*(w>>2), +32) ----
    {
        int w  = tid >> 5;
        int mt = w & 3;
        int nh = w >> 2;
        wmma::fragment<wmma::accumulator, 16, 16, 16, float> c[2];
#pragma unroll
        for (int n = 0; n < 2; n++) wmma::fill_fragment(c[n], 0.0f);
#pragma unroll
        for (int k = 0; k < 4; k++) {
            wmma::fragment<wmma::matrix_a, 16, 16, 16, __half, wmma::row_major> a;
            wmma::load_matrix_sync(a, sX + (16 * mt) * LDX + 16 * k, LDX);
#pragma unroll
            for (int n = 0; n < 2; n++) {
                wmma::fragment<wmma::matrix_b, 16, 16, 16, __half, wmma::row_major> b;
                wmma::load_matrix_sync(b, sW + (16 * k) * LDW + 16 * (2 * nh + n), LDW);
                wmma::mma_sync(c[n], a, b, c[n]);
            }
        }
#pragma unroll
        for (int n = 0; n < 2; n++)
            wmma::store_matrix_sync(sC + (16 * mt) * LDC + 16 * (2 * nh + n),
                                    c[n], LDC, wmma::mem_row_major);
    }
    __syncthreads();

    // ---- epilogue: Hh + Yinit (fp32 math, fp16 stores) ----
    for (int i = tid; i < TROWS * 16; i += 256) {
        int r = i >> 4, cg = i & 15;
        int row = row0 + r;
        if (row >= NN) continue;
        float4 h = *(float4*)&sC[r * LDC + cg * 4];
        float dv = g_dinv[row];
        // fp16 pre-scaled copy for the gather: Hh = H * dinv
        ((uint2*)g_Hh)[(size_t)row * 16 + cg] =
            f4_to_h4(make_float4(h.x * dv, h.y * dv, h.z * dv, h.w * dv));
        // Y init: bias + self-loop + residual
        float d2 = dv * dv;
        float4 b4 = __ldg(&((const float4*)bias)[cg]);
        float4 y = make_float4(b4.x + h.x * d2, b4.y + h.y * d2,
                               b4.z + h.z * d2, b4.w + h.w * d2);
        if (FP16IN && resid) {
            float4 xv = h4_to_f4(*(uint2*)&sX[r * LDX + cg * 4]); // post-ReLU
            y.x += xv.x; y.y += xv.y; y.z += xv.z; y.w += xv.w;
        }
        ((uint2*)Y)[(size_t)row * 16 + cg] = f4_to_h4(y);
    }
}

// ---------------------------------------------------------------------------
// Aggregate: one warp per node, atomic-free ELL gather (fp16 reads, fp32 acc).
//   a = Yinit[node] + dinv[node] * sum_e Hh[src_e] ;  X = relu(a)
// Final layer (classify=1): out[node] = X @ Wc + bc instead of storing X.
// ---------------------------------------------------------------------------
__global__ void __launch_bounds__(256) k_agg(int ysel,
                      const float* __restrict__ Wc,
                      const float* __restrict__ bc,
                      float* __restrict__ out, int classify) {
    int gid  = blockIdx.x * blockDim.x + threadIdx.x;
    int node = gid >> 5;
    int lane = gid & 31;

    // pre-wait: ELL metadata is final (transitively guaranteed complete)
    int k    = min(g_cur[node], ELLW);
    float dv = g_dinv[node];

    GDC_WAIT();                                  // Hh, Yinit now final
    GDC_LAUNCH();

    __half* Y = (ysel == 1) ? g_XA : g_XB;
    const int* adj = g_ell + node * ELLW;
    const __half2* H2 = (const __half2*)g_Hh;

    float2 s = make_float2(0.f, 0.f);
#pragma unroll 8
    for (int j = 0; j < k; j++) {
        int e = __ldg(&adj[j]);                  // broadcast (uniform addr)
        float2 h = __half22float2(__ldg(&H2[(size_t)e * 32 + lane]));
        s.x += h.x;
        s.y += h.y;
    }

    float2 a = __half22float2(((__half2*)Y)[(size_t)node * 32 + lane]);
    a.x = fmaxf(a.x + dv * s.x, 0.f);
    a.y = fmaxf(a.y + dv * s.y, 0.f);

    if (!classify) {
        ((__half2*)Y)[(size_t)node * 32 + lane] = __float22half2_rn(a);
    } else {
        int f = 2 * lane;                        // features f, f+1
        float c0 = a.x * __ldg(&Wc[f * 3 + 0]) + a.y * __ldg(&Wc[f * 3 + 3]);
        float c1 = a.x * __ldg(&Wc[f * 3 + 1]) + a.y * __ldg(&Wc[f * 3 + 4]);
        float c2 = a.x * __ldg(&Wc[f * 3 + 2]) + a.y * __ldg(&Wc[f * 3 + 5]);
#pragma unroll
        for (int o = 16; o > 0; o >>= 1) {
            c0 += __shfl_down_sync(0xffffffffu, c0, o);
            c1 += __shfl_down_sync(0xffffffffu, c1, o);
            c2 += __shfl_down_sync(0xffffffffu, c2, o);
        }
        if (lane == 0) {
            out[node * 3 + 0] = c0 + __ldg(&bc[0]);
            out[node * 3 + 1] = c1 + __ldg(&bc[1]);
            out[node * 3 + 2] = c2 + __ldg(&bc[2]);
        }
    }
}

// ---------------------------------------------------------------------------
template <typename F, typename... Args>
static inline void pdl(F kern, int grid, int block, size_t smem, Args... args) {
    cudaLaunchConfig_t cfg = {};
    cfg.gridDim  = dim3(grid, 1, 1);
    cfg.blockDim = dim3(block, 1, 1);
    cfg.dynamicSmemBytes = smem;
    cfg.stream   = 0;                 // same default-stream semantics as <<<>>>
    cudaLaunchAttribute attr[1];
    attr[0].id = cudaLaunchAttributeProgrammaticStreamSerialization;
    attr[0].val.programmaticStreamSerializationAllowed = 1;
    cfg.attrs = attr;
    cfg.numAttrs = 1;
    cudaLaunchKernelEx(&cfg, kern, args...);
}

extern "C" void kernel_launch(void* const* d_in, const int* in_sizes, int n_in,
                              void* d_out, int out_size) {
    const float* x  = (const float*)d_in[0];
    const void*  ei = d_in[1];
    const float* Ws = (const float*)d_in[2];
    const float* bs = (const float*)d_in[3];
    const float* Wc = (const float*)d_in[4];
    const float* bc = (const float*)d_in[5];
    float* out = (float*)d_out;

    cudaFuncSetAttribute(k_gemm<0>, cudaFuncAttributeMaxDynamicSharedMemorySize,
                         SMEM_TOTAL);
    cudaFuncSetAttribute(k_gemm<1>, cudaFuncAttributeMaxDynamicSharedMemorySize,
                         SMEM_TOTAL);

    // ---- ELL adjacency build (PDL-chained; no count/scan passes) ----
    pdl(k_init,   (NN + 255) / 256, 256, 0, (const unsigned*)ei);
    pdl(k_bucket, NE / 512, 256, 0, ei);
    pdl(k_dinv,   98, 1024, 0);

    // ---- 4 GCN layers (layer 3 fuses the classifier) ----
    const int gemm_grid = (NN + TROWS - 1) / TROWS;
    const int agg_grid  = NN * 32 / 256;
    int sel = 0;                                    // 0=x, 1=g_XA, 2=g_XB
    for (int l = 0; l < 4; l++) {
        int osel = (l & 1) ? 2 : 1;
        const float* W = Ws + l * HID * HID;
        const float* b = bs + l * HID;
        if (l == 0)
            pdl(k_gemm<0>, gemm_grid, 256, SMEM_TOTAL, x, sel, W, b, osel, 0);
        else
            pdl(k_gemm<1>, gemm_grid, 256, SMEM_TOTAL, x, sel, W, b, osel, 1);
        pdl(k_agg, agg_grid, 256, 0, osel, Wc, bc, out, (l == 3) ? 1 : 0);
        sel = osel;
    }
}